// round 17
// baseline (speedup 1.0000x reference)
#include <cuda_runtime.h>
#include <stdint.h>

#define HWC    (512*512)
#define NCH    64
#define NSEG   256
#define NB     4
#define CG     4             // channels per block
#define NCG    16            // channel groups
#define CHUNK  4096          // pixels per block = 8 image rows
#define NCHP   (HWC/CHUNK)   // 64 chunks per plane
#define TPB    256
#define NWARP  8
#define STRIP  512           // px per warp = one image row
#define TPX    128           // px per warp-tile (lane owns 4 px)
#define NT     (STRIP/TPX)   // 4 tiles per warp

// Global encoded accumulator: [b][ch][s], 256KB, L2-resident.
// Zero at load; decode_kernel re-zeroes every call (graph-replay safe).
__device__ unsigned g_enc[NB * NCH * NSEG];

// Monotone float->uint encoding; enc >= 1 for any non-NaN float, 0 = identity.
__device__ __forceinline__ unsigned enc_f32(float f) {
    unsigned b = __float_as_uint(f);
    return b ^ ((unsigned)((int)b >> 31) | 0x80000000u);
}

__global__ void __launch_bounds__(TPB, 5) seg_kernel(
    const float* __restrict__ feats,   // [B, C, 512, 512]
    const int*   __restrict__ labels)  // [B, 1, 512, 512]
{
    __shared__ unsigned smax[CG * 257];     // 4.1KB; row stride 257

    const int tid  = threadIdx.x;
    const int lane = tid & 31;
    const int w    = tid >> 5;

    const int chunk = blockIdx.x;
    const int g     = blockIdx.y;
    const int b     = blockIdx.z;
    const int row   = chunk * NWARP + w;    // this warp's image row
    const int sbase = row * 512;
    const bool ybad = (row == 0) | (row == 511);

    for (int i = tid; i < CG * 257; i += TPB) smax[i] = 0u;
    __syncthreads();

    const int*   lbp = labels + (size_t)b * HWC + sbase;
    const float* fb  = feats + (size_t)(b * NCH + g * CG) * HWC + sbase;

    // Load this lane's 16 strip labels (4 per tile), pack u8 into 4 regs.
    unsigned labp[NT];
    #pragma unroll
    for (int t = 0; t < NT; ++t) {
        int4 a = *(const int4*)(lbp + t * TPX + 4 * lane);
        labp[t] = (unsigned)(a.x & 255) | ((unsigned)(a.y & 255) << 8) |
                  ((unsigned)(a.z & 255) << 16) | ((unsigned)a.w << 24);
    }

    // Prefetch tile 0 values: lane owns px {4*lane .. 4*lane+3}.
    float4 cur[CG];
    {
        const float* fp = fb + 4 * lane;
        #pragma unroll
        for (int c = 0; c < CG; ++c)
            cur[c] = *(const float4*)(fp + (size_t)c * HWC);
    }

    #pragma unroll
    for (int t = 0; t < NT; ++t) {
        // Prefetch next tile into fresh registers (unrolled -> rotation free).
        float4 nxt[CG];
        if (t + 1 < NT) {
            const float* fp = fb + (t + 1) * TPX + 4 * lane;
            #pragma unroll
            for (int c = 0; c < CG; ++c)
                nxt[c] = *(const float4*)(fp + (size_t)c * HWC);
        }

        // Atomics straight from registers; border px -> enc 0 (max identity).
        {
            const unsigned lw = labp[t];
            const unsigned l0 = lw & 255u;
            const unsigned l1 = (lw >> 8) & 255u;
            const unsigned l2 = (lw >> 16) & 255u;
            const unsigned l3 = lw >> 24;
            // x==0 is px 0 (t0, lane0, .x); x==511 is px 511 (t=NT-1, lane31, .w)
            const bool badx = ybad | ((t == 0) & (lane == 0));
            const bool badw = ybad | ((t == NT - 1) & (lane == 31));
            #pragma unroll
            for (int c = 0; c < CG; ++c) {
                unsigned e0 = badx ? 0u : enc_f32(cur[c].x);
                unsigned e1 = ybad ? 0u : enc_f32(cur[c].y);
                unsigned e2 = ybad ? 0u : enc_f32(cur[c].z);
                unsigned e3 = badw ? 0u : enc_f32(cur[c].w);
                unsigned* rowp = smax + c * 257;
                atomicMax(rowp + l0, e0);
                atomicMax(rowp + l1, e1);
                atomicMax(rowp + l2, e2);
                atomicMax(rowp + l3, e3);
            }
        }

        #pragma unroll
        for (int c = 0; c < CG; ++c) cur[c] = nxt[c];
    }

    __syncthreads();
    // Dump: coalesced global RED.MAX into the L2-resident table.
    unsigned* gout = g_enc + (size_t)(b * NCH + g * CG) * NSEG;
    for (int i = tid; i < CG * NSEG; i += TPB)
        atomicMax(&gout[i], smax[(i >> 8) * 257 + (i & 255)]);
}

// Decode + reset, vectorized: 1 LDG.128 + 2 STG.128 per thread.
__global__ void __launch_bounds__(TPB) decode_kernel(float* __restrict__ out) {
    const int e4 = blockIdx.x * TPB + threadIdx.x;       // 0..16383
    uint4 m = ((const uint4*)g_enc)[e4];
    ((uint4*)g_enc)[e4] = make_uint4(0u, 0u, 0u, 0u);    // reset for next call
    float4 rv;
    rv.x = (m.x == 0u) ? 0.0f : __uint_as_float((m.x & 0x80000000u) ? (m.x ^ 0x80000000u) : ~m.x);
    rv.y = (m.y == 0u) ? 0.0f : __uint_as_float((m.y & 0x80000000u) ? (m.y ^ 0x80000000u) : ~m.y);
    rv.z = (m.z == 0u) ? 0.0f : __uint_as_float((m.z & 0x80000000u) ? (m.z ^ 0x80000000u) : ~m.z);
    rv.w = (m.w == 0u) ? 0.0f : __uint_as_float((m.w & 0x80000000u) ? (m.w ^ 0x80000000u) : ~m.w);
    ((float4*)out)[e4] = rv;
}

extern "C" void kernel_launch(void* const* d_in, const int* in_sizes, int n_in,
                              void* d_out, int out_size) {
    const float* feats  = (const float*)d_in[0];
    const int*   labels = (const int*)d_in[1];
    float*       out    = (float*)d_out;

    dim3 grid(NCHP, NCG, NB);                 // (64, 16, 4) = 4096 blocks
    seg_kernel<<<grid, TPB>>>(feats, labels);

    decode_kernel<<<(NB * NCH * NSEG) / (TPB * 4), TPB>>>(out);
}